// round 6
// baseline (speedup 1.0000x reference)
#include <cuda_runtime.h>
#include <cuda_bf16.h>
#include <cstdint>

#define B_    32
#define CIN_  32
#define COUT_ 64
#define H_    128
#define W_    128
#define HO_   126
#define WO_   126
#define MAXCN_ 64
#define TILES 14           // output rows per CTA strip; 9 strips x 14 = 126

__device__ float g_kdense[COUT_ * CIN_ * 9];

__global__ void fold_kernel(const float* __restrict__ w, const int* __restrict__ cn) {
    int idx = blockIdx.x * blockDim.x + threadIdx.x;
    if (idx >= COUT_ * CIN_ * 9) return;
    int k = idx % 9;
    int c = (idx / 9) % CIN_;
    int o = idx / (9 * CIN_);
    int n = cn[o];
    float v = 0.f;
    if (c < n)      v += w[(o * MAXCN_ + c) * 9 + k];
    if (c + 32 < n) v += w[(o * MAXCN_ + c + 32) * 9 + k];
    g_kdense[idx] = v;
}

// ---------------- smem layout (bytes) ----------------
// W:  [kw][hl][oc 64][k 96 pad->104] stride 208  -> 6 * 13312
// X:  ring[4][hl][px 130][c 32 pad->40] stride 80 -> 8 * 10400
// E:  transpose buffer [oc 64][wo pad 129 words]  -> 33024
#define WSTRIDE 208
#define WSIZE   13312
#define OFF_W   0
#define XSTRIDE 80
#define XSIZE   10400
#define OFF_X   79872       // 6*13312
#define OFF_E   163072      // OFF_X + 8*10400
#define SMEM_TOTAL 196096   // OFF_E + 64*129*4

__device__ __forceinline__ uint32_t smem_u32(const void* p) {
    uint32_t a;
    asm("{ .reg .u64 t; cvta.to.shared.u64 t, %1; cvt.u32.u64 %0, t; }" : "=r"(a) : "l"(p));
    return a;
}

__device__ __forceinline__ void ldsm4(uint32_t (&r)[4], uint32_t addr) {
    asm volatile("ldmatrix.sync.aligned.m8n8.x4.shared.b16 {%0,%1,%2,%3}, [%4];"
                 : "=r"(r[0]), "=r"(r[1]), "=r"(r[2]), "=r"(r[3]) : "r"(addr));
}

__device__ __forceinline__ void mma16816(float (&d)[4], const uint32_t (&a)[4],
                                         uint32_t b0, uint32_t b1) {
    asm volatile("mma.sync.aligned.m16n8k16.row.col.f32.bf16.bf16.f32 "
                 "{%0,%1,%2,%3}, {%4,%5,%6,%7}, {%8,%9}, {%0,%1,%2,%3};"
                 : "+f"(d[0]), "+f"(d[1]), "+f"(d[2]), "+f"(d[3])
                 : "r"(a[0]), "r"(a[1]), "r"(a[2]), "r"(a[3]), "r"(b0), "r"(b1));
}

__device__ __forceinline__ void cvt_split(float v, __nv_bfloat16& hi, __nv_bfloat16& lo) {
    hi = __float2bfloat16(v);
    lo = __float2bfloat16(v - __bfloat162float(hi));
}

// stage input row ir (32 c x 128 px, hi/lo) into ring slot ir&3, layout [px][c]
__device__ __forceinline__ void stage(char* smem, const float* xb, int ir, int tid) {
    char* hbase = smem + OFF_X + (size_t)((ir & 3) * 2) * XSIZE;
    for (int i = tid; i < CIN_ * W_; i += 256) {
        int c = i >> 7, px = i & 127;                 // lanes = consecutive px -> coalesced LDG
        float v = __ldg(xb + ((long)c * H_ + ir) * W_ + px);
        __nv_bfloat16 hi, lo;
        cvt_split(v, hi, lo);
        *(__nv_bfloat16*)(hbase + px * XSTRIDE + c * 2) = hi;
        *(__nv_bfloat16*)(hbase + XSIZE + px * XSTRIDE + c * 2) = lo;
    }
}

__global__ __launch_bounds__(256, 1)
void conv_kernel(const float* __restrict__ x,
                 const float* __restrict__ bias,
                 float* __restrict__ out) {
    extern __shared__ __align__(128) char smem[];
    const uint32_t sb  = smem_u32(smem);
    const int tid  = threadIdx.x;
    const int lane = tid & 31;
    const int w    = tid >> 5;
    const int b    = blockIdx.x;
    const int r0   = blockIdx.y * TILES;
    const float* xb = x + (long)b * CIN_ * H_ * W_;

    // zero the pad rows 128,129 of every X buffer (read by kw-shift for discarded wo>=126)
    for (int i = tid; i < 8 * 2 * 40; i += 256) {
        int buf = i / 80, rr = (i / 40) & 1, col = i % 40;
        *(uint16_t*)(smem + OFF_X + (size_t)buf * XSIZE + (128 + rr) * XSTRIDE + col * 2) = 0;
    }
    // stage weights: W[kw][hl][oc][k = kh*32 + c]
    for (int i = tid; i < 3 * COUT_ * 96; i += 256) {
        int k = i % 96, oc = (i / 96) & 63, kw = i / (96 * 64);
        int c = k & 31, kh = k >> 5;
        float v = g_kdense[(oc * CIN_ + c) * 9 + kh * 3 + kw];
        __nv_bfloat16 hi, lo;
        cvt_split(v, hi, lo);
        char* base = smem + OFF_W + (size_t)(kw * 2) * WSIZE + oc * WSTRIDE + k * 2;
        *(__nv_bfloat16*)base = hi;
        *(__nv_bfloat16*)(base + WSIZE) = lo;
    }
    stage(smem, xb, r0, tid);
    stage(smem, xb, r0 + 1, tid);

    const int px0 = w * 16;
    // per-lane invariant ldmatrix offsets
    const uint32_t a_lane = (uint32_t)(((lane & 7) + ((lane >> 3) & 1) * 8) * XSTRIDE
                                       + ((lane >> 4) & 1) * 16);
    const uint32_t b_lane = (uint32_t)(((lane & 7) + ((lane >> 4) & 1) * 8) * WSTRIDE
                                       + ((lane >> 3) & 1) * 16);

    for (int pl = 0; pl < TILES / 2; ++pl) {
        const int rg = r0 + 2 * pl;
        stage(smem, xb, rg + 2, tid);
        stage(smem, xb, rg + 3, tid);
        __syncthreads();

        float acc[2][8][4];
        #pragma unroll
        for (int rr = 0; rr < 2; ++rr)
            #pragma unroll
            for (int nt = 0; nt < 8; ++nt)
                #pragma unroll
                for (int j = 0; j < 4; ++j) acc[rr][nt][j] = 0.f;

        #pragma unroll
        for (int s = 0; s < 6; ++s) {
            const int kh = s >> 1;
            const uint32_t acoff = (s & 1) * 32;
            const uint32_t bcoff = (s >> 1) * 64 + (s & 1) * 32;
            #pragma unroll
            for (int kw = 0; kw < 3; ++kw) {
                // B (weight) fragments: 8 n-tiles, hi & lo
                uint32_t bh[16], bl[16];
                const uint32_t wbH = sb + OFF_W + (uint32_t)(kw * 2) * WSIZE + bcoff + b_lane;
                #pragma unroll
                for (int t = 0; t < 4; ++t) {
                    uint32_t r4[4];
                    ldsm4(r4, wbH + (uint32_t)(t * 16) * WSTRIDE);
                    bh[4 * t + 0] = r4[0]; bh[4 * t + 1] = r4[1];
                    bh[4 * t + 2] = r4[2]; bh[4 * t + 3] = r4[3];
                }
                #pragma unroll
                for (int t = 0; t < 4; ++t) {
                    uint32_t r4[4];
                    ldsm4(r4, wbH + WSIZE + (uint32_t)(t * 16) * WSTRIDE);
                    bl[4 * t + 0] = r4[0]; bl[4 * t + 1] = r4[1];
                    bl[4 * t + 2] = r4[2]; bl[4 * t + 3] = r4[3];
                }
                #pragma unroll
                for (int rr = 0; rr < 2; ++rr) {
                    const int slot = (rg + rr + kh) & 3;
                    const uint32_t xbase = sb + OFF_X + (uint32_t)(slot * 2) * XSIZE;
                    const uint32_t aaddr = xbase + (uint32_t)(px0 + kw) * XSTRIDE + acoff + a_lane;
                    uint32_t ah[4], al[4];
                    ldsm4(ah, aaddr);
                    ldsm4(al, aaddr + XSIZE);
                    #pragma unroll
                    for (int nt = 0; nt < 8; ++nt) {
                        mma16816(acc[rr][nt], ah, bh[2 * nt], bh[2 * nt + 1]);  // Xh*Wh
                        mma16816(acc[rr][nt], al, bh[2 * nt], bh[2 * nt + 1]);  // Xl*Wh
                        mma16816(acc[rr][nt], ah, bl[2 * nt], bl[2 * nt + 1]);  // Xh*Wl
                    }
                }
            }
        }

        // epilogue: per row, transpose through smem, coalesced bias+store
        #pragma unroll
        for (int rr = 0; rr < 2; ++rr) {
            const int ho = rg + rr;
            #pragma unroll
            for (int nt = 0; nt < 8; ++nt)
                #pragma unroll
                for (int j = 0; j < 4; ++j) {
                    const int oc = nt * 8 + (lane & 3) * 2 + (j & 1);
                    const int wo = px0 + (lane >> 2) + (j >> 1) * 8;
                    *(float*)(smem + OFF_E + (size_t)(oc * 129 + wo) * 4) = acc[rr][nt][j];
                }
            __syncthreads();
            for (int i = 0; i < 32; ++i) {
                const int lin = i * 256 + tid;
                const int oc = lin >> 7, wo = lin & 127;
                if (wo < WO_) {
                    float v = *(float*)(smem + OFF_E + (size_t)(oc * 129 + wo) * 4)
                            + __ldg(bias + ((long)oc * HO_ + ho) * WO_ + wo);
                    out[(((long)b * COUT_ + oc) * HO_ + ho) * WO_ + wo] = v;
                }
            }
            __syncthreads();
        }
    }
}

extern "C" void kernel_launch(void* const* d_in, const int* in_sizes, int n_in,
                              void* d_out, int out_size) {
    const float* x    = (const float*)d_in[0];   // [32,32,128,128]
    const float* w    = (const float*)d_in[1];   // [64,64,3,3]
    const float* bias = (const float*)d_in[2];   // [64,126,126]
    const int*   cn   = (const int*)d_in[3];     // [64]
    float* out = (float*)d_out;                  // [32,64,126,126]

    fold_kernel<<<(COUT_ * CIN_ * 9 + 255) / 256, 256>>>(w, cn);
    cudaFuncSetAttribute(conv_kernel, cudaFuncAttributeMaxDynamicSharedMemorySize, SMEM_TOTAL);
    conv_kernel<<<dim3(B_, 9), 256, SMEM_TOTAL>>>(x, bias, out);
}

// round 7
// speedup vs baseline: 1.0234x; 1.0234x over previous
#include <cuda_runtime.h>
#include <cuda_bf16.h>
#include <cstdint>

#define B_    32
#define CIN_  32
#define COUT_ 64
#define H_    128
#define W_    128
#define HO_   126
#define WO_   126
#define MAXCN_ 64
#define TILES 14           // output rows per CTA strip; 9 strips x 14 = 126

__device__ float g_kdense[COUT_ * CIN_ * 9];

__global__ void fold_kernel(const float* __restrict__ w, const int* __restrict__ cn) {
    int idx = blockIdx.x * blockDim.x + threadIdx.x;
    if (idx >= COUT_ * CIN_ * 9) return;
    int k = idx % 9;
    int c = (idx / 9) % CIN_;
    int o = idx / (9 * CIN_);
    int n = cn[o];
    float v = 0.f;
    if (c < n)      v += w[(o * MAXCN_ + c) * 9 + k];
    if (c + 32 < n) v += w[(o * MAXCN_ + c + 32) * 9 + k];
    g_kdense[idx] = v;
}

// ---------------- smem layout (bytes) ----------------
// W:  [kw][hl][oc 64][k 96 pad->104] stride 208  -> 6 * 13312
// X:  ring[4][hl][px 130][c 32 pad->40] stride 80 -> 8 * 10400
// E:  transpose buffer [oc 64][wo pad 129 words]  -> 33024
#define WSTRIDE 208
#define WSIZE   13312
#define OFF_W   0
#define XSTRIDE 80
#define XSIZE   10400
#define OFF_X   79872       // 6*13312
#define OFF_E   163072      // OFF_X + 8*10400
#define SMEM_TOTAL 196096   // OFF_E + 64*129*4

__device__ __forceinline__ uint32_t smem_u32(const void* p) {
    uint32_t a;
    asm("{ .reg .u64 t; cvta.to.shared.u64 t, %1; cvt.u32.u64 %0, t; }" : "=r"(a) : "l"(p));
    return a;
}

__device__ __forceinline__ void ldsm4(uint32_t (&r)[4], uint32_t addr) {
    asm volatile("ldmatrix.sync.aligned.m8n8.x4.shared.b16 {%0,%1,%2,%3}, [%4];"
                 : "=r"(r[0]), "=r"(r[1]), "=r"(r[2]), "=r"(r[3]) : "r"(addr));
}

__device__ __forceinline__ void mma16816(float (&d)[4], const uint32_t (&a)[4],
                                         uint32_t b0, uint32_t b1) {
    asm volatile("mma.sync.aligned.m16n8k16.row.col.f32.bf16.bf16.f32 "
                 "{%0,%1,%2,%3}, {%4,%5,%6,%7}, {%8,%9}, {%0,%1,%2,%3};"
                 : "+f"(d[0]), "+f"(d[1]), "+f"(d[2]), "+f"(d[3])
                 : "r"(a[0]), "r"(a[1]), "r"(a[2]), "r"(a[3]), "r"(b0), "r"(b1));
}

__device__ __forceinline__ void cvt_split(float v, __nv_bfloat16& hi, __nv_bfloat16& lo) {
    hi = __float2bfloat16(v);
    lo = __float2bfloat16(v - __bfloat162float(hi));
}

// stage input row ir (32 c x 128 px, hi/lo) into ring slot ir&3, layout [px][c]
__device__ __forceinline__ void stage(char* smem, const float* xb, int ir, int tid) {
    char* hbase = smem + OFF_X + (size_t)((ir & 3) * 2) * XSIZE;
    for (int i = tid; i < CIN_ * W_; i += 256) {
        int c = i >> 7, px = i & 127;                 // lanes = consecutive px -> coalesced LDG
        float v = __ldg(xb + ((long)c * H_ + ir) * W_ + px);
        __nv_bfloat16 hi, lo;
        cvt_split(v, hi, lo);
        *(__nv_bfloat16*)(hbase + px * XSTRIDE + c * 2) = hi;
        *(__nv_bfloat16*)(hbase + XSIZE + px * XSTRIDE + c * 2) = lo;
    }
}

__global__ __launch_bounds__(256, 1)
void conv_kernel(const float* __restrict__ x,
                 const float* __restrict__ bias,
                 float* __restrict__ out) {
    extern __shared__ __align__(128) char smem[];
    const uint32_t sb  = smem_u32(smem);
    const int tid  = threadIdx.x;
    const int lane = tid & 31;
    const int w    = tid >> 5;
    const int b    = blockIdx.x;
    const int r0   = blockIdx.y * TILES;
    const float* xb = x + (long)b * CIN_ * H_ * W_;

    // zero the pad rows 128,129 of every X buffer (read by kw-shift for discarded wo>=126)
    for (int i = tid; i < 8 * 2 * 40; i += 256) {
        int buf = i / 80, rr = (i / 40) & 1, col = i % 40;
        *(uint16_t*)(smem + OFF_X + (size_t)buf * XSIZE + (128 + rr) * XSTRIDE + col * 2) = 0;
    }
    // stage weights: W[kw][hl][oc][k = kh*32 + c]
    for (int i = tid; i < 3 * COUT_ * 96; i += 256) {
        int k = i % 96, oc = (i / 96) & 63, kw = i / (96 * 64);
        int c = k & 31, kh = k >> 5;
        float v = g_kdense[(oc * CIN_ + c) * 9 + kh * 3 + kw];
        __nv_bfloat16 hi, lo;
        cvt_split(v, hi, lo);
        char* base = smem + OFF_W + (size_t)(kw * 2) * WSIZE + oc * WSTRIDE + k * 2;
        *(__nv_bfloat16*)base = hi;
        *(__nv_bfloat16*)(base + WSIZE) = lo;
    }
    stage(smem, xb, r0, tid);
    stage(smem, xb, r0 + 1, tid);

    const int px0 = w * 16;
    // per-lane invariant ldmatrix offsets
    const uint32_t a_lane = (uint32_t)(((lane & 7) + ((lane >> 3) & 1) * 8) * XSTRIDE
                                       + ((lane >> 4) & 1) * 16);
    const uint32_t b_lane = (uint32_t)(((lane & 7) + ((lane >> 4) & 1) * 8) * WSTRIDE
                                       + ((lane >> 3) & 1) * 16);

    for (int pl = 0; pl < TILES / 2; ++pl) {
        const int rg = r0 + 2 * pl;
        stage(smem, xb, rg + 2, tid);
        stage(smem, xb, rg + 3, tid);
        __syncthreads();

        float acc[2][8][4];
        #pragma unroll
        for (int rr = 0; rr < 2; ++rr)
            #pragma unroll
            for (int nt = 0; nt < 8; ++nt)
                #pragma unroll
                for (int j = 0; j < 4; ++j) acc[rr][nt][j] = 0.f;

        #pragma unroll
        for (int s = 0; s < 6; ++s) {
            const int kh = s >> 1;
            const uint32_t acoff = (s & 1) * 32;
            const uint32_t bcoff = (s >> 1) * 64 + (s & 1) * 32;
            #pragma unroll
            for (int kw = 0; kw < 3; ++kw) {
                // B (weight) fragments: 8 n-tiles, hi & lo
                uint32_t bh[16], bl[16];
                const uint32_t wbH = sb + OFF_W + (uint32_t)(kw * 2) * WSIZE + bcoff + b_lane;
                #pragma unroll
                for (int t = 0; t < 4; ++t) {
                    uint32_t r4[4];
                    ldsm4(r4, wbH + (uint32_t)(t * 16) * WSTRIDE);
                    bh[4 * t + 0] = r4[0]; bh[4 * t + 1] = r4[1];
                    bh[4 * t + 2] = r4[2]; bh[4 * t + 3] = r4[3];
                }
                #pragma unroll
                for (int t = 0; t < 4; ++t) {
                    uint32_t r4[4];
                    ldsm4(r4, wbH + WSIZE + (uint32_t)(t * 16) * WSTRIDE);
                    bl[4 * t + 0] = r4[0]; bl[4 * t + 1] = r4[1];
                    bl[4 * t + 2] = r4[2]; bl[4 * t + 3] = r4[3];
                }
                #pragma unroll
                for (int rr = 0; rr < 2; ++rr) {
                    const int slot = (rg + rr + kh) & 3;
                    const uint32_t xbase = sb + OFF_X + (uint32_t)(slot * 2) * XSIZE;
                    const uint32_t aaddr = xbase + (uint32_t)(px0 + kw) * XSTRIDE + acoff + a_lane;
                    uint32_t ah[4], al[4];
                    ldsm4(ah, aaddr);
                    ldsm4(al, aaddr + XSIZE);
                    #pragma unroll
                    for (int nt = 0; nt < 8; ++nt) {
                        mma16816(acc[rr][nt], ah, bh[2 * nt], bh[2 * nt + 1]);  // Xh*Wh
                        mma16816(acc[rr][nt], al, bh[2 * nt], bh[2 * nt + 1]);  // Xl*Wh
                        mma16816(acc[rr][nt], ah, bl[2 * nt], bl[2 * nt + 1]);  // Xh*Wl
                    }
                }
            }
        }

        // epilogue: per row, transpose through smem, coalesced bias+store
        #pragma unroll
        for (int rr = 0; rr < 2; ++rr) {
            const int ho = rg + rr;
            #pragma unroll
            for (int nt = 0; nt < 8; ++nt)
                #pragma unroll
                for (int j = 0; j < 4; ++j) {
                    const int oc = nt * 8 + (lane & 3) * 2 + (j & 1);
                    const int wo = px0 + (lane >> 2) + (j >> 1) * 8;
                    *(float*)(smem + OFF_E + (size_t)(oc * 129 + wo) * 4) = acc[rr][nt][j];
                }
            __syncthreads();
            for (int i = 0; i < 32; ++i) {
                const int lin = i * 256 + tid;
                const int oc = lin >> 7, wo = lin & 127;
                if (wo < WO_) {
                    float v = *(float*)(smem + OFF_E + (size_t)(oc * 129 + wo) * 4)
                            + __ldg(bias + ((long)oc * HO_ + ho) * WO_ + wo);
                    out[(((long)b * COUT_ + oc) * HO_ + ho) * WO_ + wo] = v;
                }
            }
            __syncthreads();
        }
    }
}

extern "C" void kernel_launch(void* const* d_in, const int* in_sizes, int n_in,
                              void* d_out, int out_size) {
    const float* x    = (const float*)d_in[0];   // [32,32,128,128]
    const float* w    = (const float*)d_in[1];   // [64,64,3,3]
    const float* bias = (const float*)d_in[2];   // [64,126,126]
    const int*   cn   = (const int*)d_in[3];     // [64]
    float* out = (float*)d_out;                  // [32,64,126,126]

    fold_kernel<<<(COUT_ * CIN_ * 9 + 255) / 256, 256>>>(w, cn);
    cudaFuncSetAttribute(conv_kernel, cudaFuncAttributeMaxDynamicSharedMemorySize, SMEM_TOTAL);
    conv_kernel<<<dim3(B_, 9), 256, SMEM_TOTAL>>>(x, bias, out);
}